// round 1
// baseline (speedup 1.0000x reference)
#include <cuda_runtime.h>

#define N 4096
#define D 512
#define NCLASS 100

__device__ float g_zn[N * D];      // normalized z
__device__ float g_eadv[N];        // exp(cos(z, z_adv)/T)
__device__ float g_loss[N];
__device__ int   g_count[NCLASS];
__device__ int   g_offset[NCLASS];
__device__ int   g_members[N];     // row indices grouped by class, ascending within class
__device__ int   g_is64;

__constant__ float c_invT = 2.0f;  // 1 / 0.5
__constant__ float c_eps  = 1e-8f;

__device__ __forceinline__ int get_label(const int* lab, int i, int is64) {
    // little-endian: low word of a non-negative int64 is the value
    return is64 ? lab[2 * i] : lab[i];
}

// ---------------------------------------------------------------------------
// Detect labels dtype: if int64, words[2k+1]==0 and words[2k] in [0,100).
// With random int32 labels, odd words are labels and virtually certainly
// contain a nonzero -> is64=0. Deterministic for a given input.
// ---------------------------------------------------------------------------
__global__ void k_detect(const int* __restrict__ lab32) {
    __shared__ int ok;
    if (threadIdx.x == 0) ok = 1;
    __syncthreads();
    bool good = true;
    for (int k = threadIdx.x; k < N / 2; k += blockDim.x) {
        int lo = lab32[2 * k];
        int hi = lab32[2 * k + 1];
        if (hi != 0 || lo < 0 || lo >= NCLASS) good = false;
    }
    if (!good) atomicExch(&ok, 0);
    __syncthreads();
    if (threadIdx.x == 0) g_is64 = ok;
}

// ---------------------------------------------------------------------------
// Per-row: normalize z into g_zn, compute e_adv = exp(cos(z,z_adv)/T).
// 128 threads/block, one block per row, float4 loads.
// ---------------------------------------------------------------------------
__global__ void k_norm(const float* __restrict__ z, const float* __restrict__ za) {
    int row = blockIdx.x;
    int t = threadIdx.x;  // 0..127
    const float4* zr  = reinterpret_cast<const float4*>(z  + (size_t)row * D);
    const float4* zar = reinterpret_cast<const float4*>(za + (size_t)row * D);
    float4 v = zr[t];
    float4 w = zar[t];
    float sz = v.x * v.x + v.y * v.y + v.z * v.z + v.w * v.w;
    float sa = w.x * w.x + w.y * w.y + w.z * w.z + w.w * w.w;
    float dd = v.x * w.x + v.y * w.y + v.z * w.z + v.w * w.w;
#pragma unroll
    for (int o = 16; o; o >>= 1) {
        sz += __shfl_xor_sync(0xffffffffu, sz, o);
        sa += __shfl_xor_sync(0xffffffffu, sa, o);
        dd += __shfl_xor_sync(0xffffffffu, dd, o);
    }
    __shared__ float s1[4], s2[4], s3[4];
    int wid = t >> 5, lid = t & 31;
    if (lid == 0) { s1[wid] = sz; s2[wid] = sa; s3[wid] = dd; }
    __syncthreads();
    sz = s1[0] + s1[1] + s1[2] + s1[3];
    sa = s2[0] + s2[1] + s2[2] + s2[3];
    dd = s3[0] + s3[1] + s3[2] + s3[3];

    float invz  = 1.0f / fmaxf(sqrtf(sz), c_eps);
    float invza = 1.0f / fmaxf(sqrtf(sa), c_eps);

    float4 o4 = make_float4(v.x * invz, v.y * invz, v.z * invz, v.w * invz);
    reinterpret_cast<float4*>(g_zn + (size_t)row * D)[t] = o4;

    if (t == 0) g_eadv[row] = expf(dd * invz * invza * c_invT);
}

// ---------------------------------------------------------------------------
// Class histogram + exclusive scan. One block.
// ---------------------------------------------------------------------------
__global__ void k_hist(const int* __restrict__ lab) {
    __shared__ int cnt[NCLASS];
    int t = threadIdx.x;
    for (int c = t; c < NCLASS; c += blockDim.x) cnt[c] = 0;
    __syncthreads();
    int is64 = g_is64;
    for (int i = t; i < N; i += blockDim.x)
        atomicAdd(&cnt[get_label(lab, i, is64)], 1);
    __syncthreads();
    if (t == 0) {
        int off = 0;
        for (int c = 0; c < NCLASS; c++) {
            g_offset[c] = off;
            g_count[c] = cnt[c];
            off += cnt[c];
        }
    }
}

// ---------------------------------------------------------------------------
// Deterministic scatter: warp per row i computes rank = #{j<i: label_j==c},
// writes g_members[offset[c]+rank] = i. No atomics -> deterministic order.
// ---------------------------------------------------------------------------
__global__ void k_rank(const int* __restrict__ lab) {
    int w = (blockIdx.x * blockDim.x + threadIdx.x) >> 5;
    int lane = threadIdx.x & 31;
    if (w >= N) return;
    int is64 = g_is64;
    int c = get_label(lab, w, is64);
    int r = 0;
    for (int j = lane; j < w; j += 32)
        r += (get_label(lab, j, is64) == c) ? 1 : 0;
#pragma unroll
    for (int o = 16; o; o >>= 1) r += __shfl_xor_sync(0xffffffffu, r, o);
    if (lane == 0) g_members[g_offset[c] + r] = w;
}

// ---------------------------------------------------------------------------
// Main: warp per member slot s. i = g_members[s] so adjacent warps share a
// class -> the class's rows stay hot in L1. Row i held in 4 float4 regs;
// stream class members j, dot + butterfly reduce + expf.
// ---------------------------------------------------------------------------
__global__ void k_intra(const int* __restrict__ lab) {
    int s = (blockIdx.x * blockDim.x + threadIdx.x) >> 5;
    int lane = threadIdx.x & 31;
    if (s >= N) return;
    int i = g_members[s];
    int c = get_label(lab, i, g_is64);
    int off = g_offset[c];
    int cnt = g_count[c];

    const float4* zi = reinterpret_cast<const float4*>(g_zn + (size_t)i * D);
    float4 r[4];
#pragma unroll
    for (int k = 0; k < 4; k++) r[k] = zi[lane + 32 * k];

    float acc = 0.0f;
    for (int m = 0; m < cnt; m++) {
        int j = g_members[off + m];
        if (j == i) continue;
        const float4* zj = reinterpret_cast<const float4*>(g_zn + (size_t)j * D);
        float sdot = 0.0f;
#pragma unroll
        for (int k = 0; k < 4; k++) {
            float4 b = zj[lane + 32 * k];
            sdot += r[k].x * b.x;
            sdot += r[k].y * b.y;
            sdot += r[k].z * b.z;
            sdot += r[k].w * b.w;
        }
#pragma unroll
        for (int o = 16; o; o >>= 1) sdot += __shfl_xor_sync(0xffffffffu, sdot, o);
        acc += expf(sdot * c_invT);
    }
    if (lane == 0) g_loss[i] = log1pf(acc / g_eadv[i]);
}

// ---------------------------------------------------------------------------
// Final reduction: out[0] = sum(loss)/N. Single block.
// ---------------------------------------------------------------------------
__global__ void k_reduce(float* __restrict__ out) {
    __shared__ float sm[256];
    int t = threadIdx.x;
    float s = 0.0f;
    for (int i = t; i < N; i += 256) s += g_loss[i];
    sm[t] = s;
    __syncthreads();
    for (int o = 128; o; o >>= 1) {
        if (t < o) sm[t] += sm[t + o];
        __syncthreads();
    }
    if (t == 0) out[0] = sm[0] * (1.0f / (float)N);
}

extern "C" void kernel_launch(void* const* d_in, const int* in_sizes, int n_in,
                              void* d_out, int out_size) {
    const float* z   = (const float*)d_in[0];
    const float* za  = (const float*)d_in[1];
    const int*   lab = (const int*)d_in[2];
    float* out = (float*)d_out;

    k_detect<<<1, 256>>>(lab);
    k_norm<<<N, 128>>>(z, za);
    k_hist<<<1, 128>>>(lab);
    k_rank<<<N / 8, 256>>>(lab);    // 4096 warps, 8 warps/block
    k_intra<<<N / 8, 256>>>(lab);   // 4096 warps, 8 warps/block
    k_reduce<<<1, 256>>>(out);
}